// round 8
// baseline (speedup 1.0000x reference)
#include <cuda_runtime.h>
#include <cuda_fp16.h>
#include <cstdint>

// ---------------- problem dims ----------------
#define T_DIM 8192
#define D_DIM 1024
#define H_DIM 4096

// scratch (device globals: no allocation allowed)
__device__ __half g_h  [(size_t)T_DIM * H_DIM];   // 64 MB intermediate (fp16)
__device__ __half g_xh [(size_t)T_DIM * D_DIM];   // fp16 x
__device__ __half g_wfc[(size_t)H_DIM * D_DIM];   // fp16 W_fc
__device__ __half g_wpr[(size_t)D_DIM * H_DIM];   // fp16 W_proj

// ---------------- helpers ----------------
__device__ __forceinline__ uint32_t smem_u32(const void* p) {
    uint32_t a;
    asm("{ .reg .u64 t; cvta.to.shared.u64 t, %1; cvt.u32.u64 %0, t; }" : "=r"(a) : "l"(p));
    return a;
}
__device__ __forceinline__ uint32_t swz(uint32_t b) {   // SW128: XOR bits[6:4] with bits[9:7]
    return b ^ ((b >> 3) & 0x70u);
}
__device__ __forceinline__ void cp_async16(uint32_t saddr, const void* g) {
    asm volatile("cp.async.cg.shared.global [%0], [%1], 16;" :: "r"(saddr), "l"(g));
}

#define MBARRIER_INIT(addr, cnt) \
    asm volatile("mbarrier.init.shared.b64 [%0], %1;" :: "r"((uint32_t)(addr)), "r"((uint32_t)(cnt)) : "memory")
#define MBARRIER_ARRIVE(addr) \
    asm volatile("mbarrier.arrive.shared.b64 _, [%0];" :: "r"((uint32_t)(addr)) : "memory")
#define CPASYNC_MBAR_ARRIVE(addr) \
    asm volatile("cp.async.mbarrier.arrive.noinc.shared.b64 [%0];" :: "r"((uint32_t)(addr)) : "memory")
#define MBARRIER_WAIT_PARITY(addr, par) do { \
    uint32_t _m = (uint32_t)(addr); uint32_t _p = (uint32_t)(par); uint32_t _d; \
    asm volatile("{\n\t.reg .pred p;\n\tmbarrier.try_wait.parity.acquire.cta.shared::cta.b64 p, [%1], %2;\n\tselp.b32 %0, 1, 0, p;\n\t}" \
        : "=r"(_d) : "r"(_m), "r"(_p) : "memory"); \
    if (!_d) { \
        asm volatile("{\n\t.reg .pred P1;\n\tWL_%=:\n\tmbarrier.try_wait.parity.acquire.cta.shared::cta.b64 P1, [%0], %1, 0x989680;\n\t@P1 bra.uni WD_%=;\n\tbra.uni WL_%=;\n\tWD_%=:\n\t}" \
            :: "r"(_m), "r"(_p) : "memory"); \
    } } while (0)

#define LDSM_X4(r0, r1, r2, r3, addr) \
    asm volatile("ldmatrix.sync.aligned.m8n8.x4.shared.b16 {%0,%1,%2,%3}, [%4];" \
        : "=r"(r0), "=r"(r1), "=r"(r2), "=r"(r3) : "r"(addr))

// fp16 MMA, fp32 accumulate: D(16x8) += A(16x16) * B(16x8)
#define MMA_F16(c0, c1, c2, c3, a0, a1, a2, a3, b0, b1) \
    asm volatile("mma.sync.aligned.m16n8k16.row.col.f32.f16.f16.f32 " \
        "{%0,%1,%2,%3}, {%4,%5,%6,%7}, {%8,%9}, {%0,%1,%2,%3};" \
        : "+f"(c0), "+f"(c1), "+f"(c2), "+f"(c3) \
        : "r"(a0), "r"(a1), "r"(a2), "r"(a3), "r"(b0), "r"(b1))

// ---------------- GEMM config ----------------
static constexpr int BLK_M = 128;
static constexpr int BLK_N = 128;
static constexpr int BLK_K = 64;                 // fp16 elems -> 128 bytes per row
static constexpr int STAGES = 3;
static constexpr int A_BYTES = BLK_M * BLK_K * 2;          // 16384
static constexpr int B_BYTES = BLK_N * BLK_K * 2;          // 16384
static constexpr int STAGE_BYTES = A_BYTES + B_BYTES;      // 32768
static constexpr int DATA_BYTES = STAGES * STAGE_BYTES;    // 98304
static constexpr int SMEM_TOTAL = DATA_BYTES + 128;        // + mbarriers
// barriers: full[s] = DATA_BYTES + 16*s ; empty[s] = DATA_BYTES + 16*s + 8

// OUT16: write C as fp16 (GEMM1 -> h). Otherwise fp32.
template <bool RELU2, bool OUT16>
__global__ void __launch_bounds__(288, 2) gemm_f16_mma(
    const __half* __restrict__ A,   // [M, K] row-major (K contiguous)
    const __half* __restrict__ B,   // [N, K] row-major (K contiguous)
    void* __restrict__ Cv,          // [M, N]
    int K, int ldc)
{
    extern __shared__ char smem[];
    const uint32_t sb = smem_u32(smem);
    const int tid  = threadIdx.x;
    const int lane = tid & 31;
    const int warp = tid >> 5;
    const int KT = K / BLK_K;

    if (tid == 0) {
        #pragma unroll
        for (int s = 0; s < STAGES; ++s) {
            MBARRIER_INIT(sb + DATA_BYTES + 16 * s, 32);      // full: 32 producer lanes
            MBARRIER_INIT(sb + DATA_BYTES + 16 * s + 8, 8);   // empty: 8 consumer warps
        }
    }
    __syncthreads();

    if (warp == 8) {
        // ---------------- producer warp ----------------
        const __half* gA = A + (size_t)blockIdx.x * BLK_M * K;
        const __half* gB = B + (size_t)blockIdx.y * BLK_N * K;
        // lane handles chunks lane, lane+32, ... (chunk = 16B unit; 8 units per 128B row)
        const uint32_t offL = (uint32_t)(lane >> 3) * 128 + (uint32_t)(lane & 7) * 16;
        const __half* pA = gA + (size_t)(lane >> 3) * K + (lane & 7) * 8;
        const __half* pB = gB + (size_t)(lane >> 3) * K + (lane & 7) * 8;

        int st = 0, ph = 1;
        for (int kt = 0; kt < KT; ++kt) {
            MBARRIER_WAIT_PARITY(sb + DATA_BYTES + 16 * st + 8, ph);   // empty
            const uint32_t base = sb + st * STAGE_BYTES;
            const int k0 = kt * BLK_K;
            #pragma unroll
            for (int i = 0; i < 32; ++i)        // A: 1024 chunks / 32 lanes
                cp_async16(base + swz(offL + i * 512), pA + (size_t)i * 4 * K + k0);
            #pragma unroll
            for (int i = 0; i < 32; ++i)        // B
                cp_async16(base + A_BYTES + swz(offL + i * 512), pB + (size_t)i * 4 * K + k0);
            CPASYNC_MBAR_ARRIVE(sb + DATA_BYTES + 16 * st);            // full when done
            if (++st == STAGES) { st = 0; ph ^= 1; }
        }
        return;
    }

    // ---------------- consumer warps 0-7 ----------------
    const int wm = (warp & 3) * 32;        // warp grid 4x2, warp tile 32x64
    const int wn = (warp >> 2) * 64;

    const uint32_t xmask = (uint32_t)(lane & 7) << 4;
    const uint32_t aLin0 = (uint32_t)(wm + (lane & 15)) * 128 + (uint32_t)(lane >> 4) * 16;
    const uint32_t aLin1 = aLin0 + 16 * 128;
    uint32_t bLin[4];
    #pragma unroll
    for (int jp = 0; jp < 4; ++jp)
        bLin[jp] = (uint32_t)(wn + jp * 16 + (lane & 15)) * 128 + (uint32_t)(lane >> 4) * 16;

    float c[2][8][4];
    #pragma unroll
    for (int mi = 0; mi < 2; ++mi)
        #pragma unroll
        for (int j = 0; j < 8; ++j)
            #pragma unroll
            for (int q = 0; q < 4; ++q) c[mi][j][q] = 0.0f;

    int st = 0, ph = 0;
    for (int kt = 0; kt < KT; ++kt) {
        MBARRIER_WAIT_PARITY(sb + DATA_BYTES + 16 * st, ph);           // full
        const uint32_t stb = sb + st * STAGE_BYTES;

        #pragma unroll
        for (int s = 0; s < 4; ++s) {              // 4 x K=16 steps (32B each)
            const uint32_t add = s * 32;
            uint32_t a[2][4], b[4][4];
            LDSM_X4(a[0][0], a[0][1], a[0][2], a[0][3], stb + ((aLin0 + add) ^ xmask));
            LDSM_X4(a[1][0], a[1][1], a[1][2], a[1][3], stb + ((aLin1 + add) ^ xmask));
            #pragma unroll
            for (int jp = 0; jp < 4; ++jp)
                LDSM_X4(b[jp][0], b[jp][1], b[jp][2], b[jp][3],
                        stb + A_BYTES + ((bLin[jp] + add) ^ xmask));
            #pragma unroll
            for (int mi = 0; mi < 2; ++mi)
                #pragma unroll
                for (int jp = 0; jp < 4; ++jp) {
                    MMA_F16(c[mi][2 * jp][0], c[mi][2 * jp][1], c[mi][2 * jp][2], c[mi][2 * jp][3],
                            a[mi][0], a[mi][1], a[mi][2], a[mi][3], b[jp][0], b[jp][2]);
                    MMA_F16(c[mi][2 * jp + 1][0], c[mi][2 * jp + 1][1], c[mi][2 * jp + 1][2], c[mi][2 * jp + 1][3],
                            a[mi][0], a[mi][1], a[mi][2], a[mi][3], b[jp][1], b[jp][3]);
                }
        }

        if (lane == 0) MBARRIER_ARRIVE(sb + DATA_BYTES + 16 * st + 8); // empty
        if (++st == STAGES) { st = 0; ph ^= 1; }
    }

    // epilogue
    const int row0 = blockIdx.x * BLK_M + wm + (lane >> 2);
    const int col0 = blockIdx.y * BLK_N + wn + (lane & 3) * 2;
    #pragma unroll
    for (int mi = 0; mi < 2; ++mi)
        #pragma unroll
        for (int rr = 0; rr < 2; ++rr) {
            const int row = row0 + mi * 16 + rr * 8;
            #pragma unroll
            for (int j = 0; j < 8; ++j) {
                float v0 = c[mi][j][rr * 2], v1 = c[mi][j][rr * 2 + 1];
                if (RELU2) {
                    v0 = fmaxf(v0, 0.0f); v0 *= v0;
                    v1 = fmaxf(v1, 0.0f); v1 *= v1;
                }
                if (OUT16) {
                    __half* base = (__half*)Cv + (size_t)row * ldc + col0;
                    __half2 hv = __floats2half2_rn(v0, v1);
                    *reinterpret_cast<__half2*>(base + j * 8) = hv;
                } else {
                    float* base = (float*)Cv + (size_t)row * ldc + col0;
                    *reinterpret_cast<float2*>(base + j * 8) = make_float2(v0, v1);
                }
            }
        }
}

// ---------------- fp32 -> fp16 RN pre-pass ----------------
__global__ void to_half_kernel(const float4* __restrict__ in, __half2* __restrict__ out, int n4)
{
    int i = blockIdx.x * blockDim.x + threadIdx.x;
    if (i >= n4) return;
    float4 v = in[i];
    out[2 * i]     = __floats2half2_rn(v.x, v.y);
    out[2 * i + 1] = __floats2half2_rn(v.z, v.w);
}

// ---------------- host side ----------------
extern "C" void kernel_launch(void* const* d_in, const int* in_sizes, int n_in,
                              void* d_out, int out_size)
{
    const float* x   = (const float*)d_in[0];  // [8192, 1024]
    const float* wfc = (const float*)d_in[1];  // [4096, 1024]
    const float* wpr = (const float*)d_in[2];  // [1024, 4096]
    float* out = (float*)d_out;                // [8192, 1024]

    __half *h, *xh, *wfch, *wprh;
    cudaGetSymbolAddress((void**)&h,    g_h);
    cudaGetSymbolAddress((void**)&xh,   g_xh);
    cudaGetSymbolAddress((void**)&wfch, g_wfc);
    cudaGetSymbolAddress((void**)&wprh, g_wpr);

    cudaFuncSetAttribute(gemm_f16_mma<true, true>,
                         cudaFuncAttributeMaxDynamicSharedMemorySize, SMEM_TOTAL);
    cudaFuncSetAttribute(gemm_f16_mma<false, false>,
                         cudaFuncAttributeMaxDynamicSharedMemorySize, SMEM_TOTAL);

    // fp32 -> fp16 (RN) pre-pass; fp16 mantissa == tf32 mantissa (11 bits effective)
    {
        int n4x = T_DIM * D_DIM / 4;
        int n4f = H_DIM * D_DIM / 4;
        int n4p = D_DIM * H_DIM / 4;
        to_half_kernel<<<(n4x + 255) / 256, 256>>>((const float4*)x,   (__half2*)xh,   n4x);
        to_half_kernel<<<(n4f + 255) / 256, 256>>>((const float4*)wfc, (__half2*)wfch, n4f);
        to_half_kernel<<<(n4p + 255) / 256, 256>>>((const float4*)wpr, (__half2*)wprh, n4p);
    }

    // GEMM1: h = relu(x @ Wfc^T)^2   [8192, 4096], K = 1024, out fp16
    gemm_f16_mma<true, true><<<dim3(T_DIM / BLK_M, H_DIM / BLK_N), 288, SMEM_TOTAL>>>(
        xh, wfch, h, D_DIM, H_DIM);

    // GEMM2: out = h @ Wpr^T         [8192, 1024], K = 4096, out fp32
    gemm_f16_mma<false, false><<<dim3(T_DIM / BLK_M, D_DIM / BLK_N), 288, SMEM_TOTAL>>>(
        h, wprh, out, H_DIM, D_DIM);
}